// round 14
// baseline (speedup 1.0000x reference)
#include <cuda_runtime.h>
#include <cuda_fp16.h>
#include <math.h>
#include <float.h>
#include <stdint.h>

#define TT   512
#define BB   8
#define DD   512
#define HH   8
#define DHH  64
#define RR   1023
#define BHN  64
#define MROWS 4096

// ---------------- scratch (fp16 payloads) ----------------
__device__ __half g_q[BHN * TT * DHH];      // [b*8+h][t][dh]
__device__ __half g_k[BHN * TT * DHH];
__device__ __half g_vT[BHN * DHH * TT];     // [b*8+h][dh][t]
__device__ __half g_rpe[RR * DD];           // [r][h*64+dh]
__device__ __half g_wqh[1536 * 512];        // W_qkv^T [n][k]
__device__ __half g_wph[512 * 512];         // W_pos^T [n][k]
__device__ __half g_woh[512 * 512];         // W_out^T [n][k]
__device__ __half g_aoh[MROWS * DD];        // attention out (t,b,d), half
__device__ float  g_uk[BHN * TT];
__device__ float  g_vr[RR * HH];

__device__ __forceinline__ void mma16(float* c, const uint32_t* a, const uint32_t* b) {
    asm volatile(
        "mma.sync.aligned.m16n8k16.row.col.f32.f16.f16.f32 "
        "{%0,%1,%2,%3},{%4,%5,%6,%7},{%8,%9},{%0,%1,%2,%3};"
        : "+f"(c[0]), "+f"(c[1]), "+f"(c[2]), "+f"(c[3])
        : "r"(a[0]), "r"(a[1]), "r"(a[2]), "r"(a[3]), "r"(b[0]), "r"(b[1]));
}

__device__ __forceinline__ uint32_t packh2(float lo, float hi) {
    __half2 h = __floats2half2_rn(lo, hi);
    return *(uint32_t*)&h;
}

__device__ __forceinline__ uint32_t smem_u32(const void* p) {
    uint32_t a;
    asm("{ .reg .u64 t; cvta.to.shared.u64 t, %1; cvt.u32.u64 %0, t; }" : "=r"(a) : "l"(p));
    return a;
}

__device__ __forceinline__ void ldm_x4(uint32_t* d, uint32_t addr) {
    asm volatile(
        "ldmatrix.sync.aligned.m8n8.x4.shared.b16 {%0,%1,%2,%3}, [%4];"
        : "=r"(d[0]), "=r"(d[1]), "=r"(d[2]), "=r"(d[3]) : "r"(addr));
}

// ============================================================================
// PREP: weight transposes only. [0,768) Wqkv^T; [768,1024) Wpos^T; [1024,1280) Wout^T
// ============================================================================
__global__ void __launch_bounds__(256)
prep_kernel(const float* __restrict__ Wqkv, const float* __restrict__ Wpos,
            const float* __restrict__ Wout) {
    __shared__ float t[32][33];
    int bid = blockIdx.x, tid = threadIdx.x;

    const float* src; __half* dst; int N, bx, by;
    if (bid < 768)       { int b = bid;        src = Wqkv; dst = g_wqh; N = 1536; bx = b % 48, by = b / 48; }
    else if (bid < 1024) { int b = bid - 768;  src = Wpos; dst = g_wph; N = 512;  bx = b % 16, by = b / 16; }
    else                 { int b = bid - 1024; src = Wout; dst = g_woh; N = 512;  bx = b % 16, by = b / 16; }

    int n0 = bx * 32, k0 = by * 32;
    int tx = tid & 31, ty = tid >> 5;
    for (int r = ty; r < 32; r += 8)
        t[r][tx] = src[(size_t)(k0 + r) * N + n0 + tx];
    __syncthreads();
    for (int r = ty; r < 32; r += 8)
        dst[(size_t)(n0 + r) * 512 + k0 + tx] = __float2half(t[tx][r]);
}

// ============================================================================
// FUSED GEMM: QKV (x read fp32 directly) + rpe, with uk/vr fused in epilogue.
// 128x64 tile, occ 3, ldmatrix fragment loads.
// ============================================================================
__global__ void __launch_bounds__(256, 3)
gemm_fused_kernel(const float* __restrict__ x,
                  const float* __restrict__ pos_u,
                  const float* __restrict__ pos_v) {
    __shared__ uint32_t As[128 * 36];
    __shared__ uint32_t Bs[64 * 36];
    __shared__ float freqs[512];
    const int bid = blockIdx.x, tid = threadIdx.x;
    const int lane = tid & 31, wid = tid >> 5;
    const int wm = wid >> 1, wn = wid & 1;
    const int gi = lane >> 2, ti = lane & 3;

    const int lr = lane & 7;
    const int arow = lr + ((lane >> 3) & 1) * 8;
    const int acol = (lane >> 4) * 4;
    const int brow = lr + ((lane >> 4) & 1) * 8;
    const int bcol = ((lane >> 3) & 1) * 4;
    const uint32_t asb = smem_u32(As);
    const uint32_t bsb = smem_u32(Bs);

    const bool is_rpe = (bid >= 768);
    int m0, n0;
    const uint32_t* bw;
    if (!is_rpe) {
        m0 = (bid / 24) * 128; n0 = (bid % 24) * 64;
        bw = (const uint32_t*)g_wqh;
    } else {
        int b = bid - 768;
        m0 = (b / 8) * 128; n0 = (b % 8) * 64;
        bw = (const uint32_t*)g_wph;
        for (int s = tid; s < 512; s += 256) {
            int cc = s & 255;
            freqs[s] = __expf(-9.210340371976184f * (float)cc * (1.0f / 256.0f));
        }
        __syncthreads();
    }

    float c_[2][4][4] = {};

    for (int k0 = 0; k0 < 8; ++k0) {
        if (!is_rpe) {
#pragma unroll
            for (int rep = 0; rep < 8; ++rep) {
                int s = rep * 256 + tid;            // 2048 float4 slots
                int row = s >> 4, seg = s & 15;
                float4 v = *(const float4*)&x[(size_t)(m0 + row) * 512 + k0 * 64 + seg * 4];
                *(uint2*)&As[row * 36 + seg * 2] =
                    make_uint2(packh2(v.x, v.y), packh2(v.z, v.w));
            }
        } else {
#pragma unroll
            for (int rep = 0; rep < 16; ++rep) {
                int s = rep * 256 + tid;
                int row = s >> 5, w = s & 31;
                int kg = k0 * 64 + 2 * w;
                float rel = (float)(m0 + row - 511);
                float a0 = rel * freqs[kg], a1 = rel * freqs[kg + 1];
                float f0 = (kg < 256) ? sinf(a0) : cosf(a0);
                float f1 = (kg + 1 < 256) ? sinf(a1) : cosf(a1);
                As[row * 36 + w] = packh2(f0, f1);
            }
        }
#pragma unroll
        for (int rep = 0; rep < 2; ++rep) {
            int s = rep * 256 + tid;
            int row = s >> 3, seg = s & 7;
            *(uint4*)&Bs[row * 36 + seg * 4] =
                *(const uint4*)&bw[(size_t)(n0 + row) * 256 + k0 * 32 + seg * 4];
        }
        __syncthreads();
#pragma unroll
        for (int kb = 0; kb < 4; ++kb) {
            uint32_t a[2][4], bq[2][4];
#pragma unroll
            for (int mt = 0; mt < 2; ++mt)
                ldm_x4(a[mt], asb + (uint32_t)(((wm * 32 + mt * 16 + arow) * 36
                                                + kb * 8 + acol) * 4));
#pragma unroll
            for (int p = 0; p < 2; ++p)
                ldm_x4(bq[p], bsb + (uint32_t)(((wn * 32 + p * 16 + brow) * 36
                                                + kb * 8 + bcol) * 4));
#pragma unroll
            for (int mt = 0; mt < 2; ++mt)
#pragma unroll
                for (int p = 0; p < 2; ++p) {
                    mma16(c_[mt][p * 2],     a[mt], &bq[p][0]);
                    mma16(c_[mt][p * 2 + 1], a[mt], &bq[p][2]);
                }
        }
        __syncthreads();
    }

    if (!is_rpe) {
        const int part = n0 >> 9, hh = (n0 >> 6) & 7;
        float biasacc[2][2] = {};                   // [mt][half]
#pragma unroll
        for (int mt = 0; mt < 2; ++mt) {
            int m = m0 + wm * 32 + mt * 16 + gi;
#pragma unroll
            for (int nt = 0; nt < 4; ++nt) {
                int n = n0 + wn * 32 + nt * 8 + 2 * ti;
                int dh = n & 63;
                float pu0 = 0.f, pu1 = 0.f;
                if (part == 1) {
                    pu0 = pos_u[hh * 64 + dh];
                    pu1 = pos_u[hh * 64 + dh + 1];
                }
#pragma unroll
                for (int half = 0; half < 2; ++half) {
                    int mm = m + half * 8;
                    float v0 = c_[mt][nt][half * 2], v1 = c_[mt][nt][half * 2 + 1];
                    int tr = mm >> 3, bi = mm & 7;
                    int bh = bi * 8 + hh;
                    if (part == 2) {
                        g_vT[((size_t)bh * 64 + dh) * 512 + tr]     = __float2half(v0);
                        g_vT[((size_t)bh * 64 + dh + 1) * 512 + tr] = __float2half(v1);
                    } else {
                        __half* dst = (part == 0) ? g_q : g_k;
                        *(uint32_t*)&dst[((size_t)bh * 512 + tr) * 64 + dh] = packh2(v0, v1);
                        if (part == 1) biasacc[mt][half] += pu0 * v0 + pu1 * v1;
                    }
                }
            }
        }
        if (part == 1) {
#pragma unroll
            for (int mt = 0; mt < 2; ++mt)
#pragma unroll
                for (int half = 0; half < 2; ++half) {
                    float p = biasacc[mt][half];
                    p += __shfl_xor_sync(0xffffffffu, p, 1);
                    p += __shfl_xor_sync(0xffffffffu, p, 2);
                    if (ti == 0) {
                        int mm = m0 + wm * 32 + mt * 16 + gi + half * 8;
                        int tr = mm >> 3, bi = mm & 7;
                        atomicAdd(&g_uk[(bi * 8 + hh) * 512 + tr], p);
                    }
                }
        }
    } else {
        const int h = n0 >> 6;
        float biasacc[2][2] = {};
#pragma unroll
        for (int mt = 0; mt < 2; ++mt) {
            int m = m0 + wm * 32 + mt * 16 + gi;
#pragma unroll
            for (int nt = 0; nt < 4; ++nt) {
                int n = n0 + wn * 32 + nt * 8 + 2 * ti;
                int dh = n & 63;
                float pv0 = pos_v[h * 64 + dh];
                float pv1 = pos_v[h * 64 + dh + 1];
                if (m < RR) {
                    *(uint32_t*)&g_rpe[(size_t)m * 512 + n] = packh2(c_[mt][nt][0], c_[mt][nt][1]);
                    biasacc[mt][0] += pv0 * c_[mt][nt][0] + pv1 * c_[mt][nt][1];
                }
                if (m + 8 < RR) {
                    *(uint32_t*)&g_rpe[(size_t)(m + 8) * 512 + n] = packh2(c_[mt][nt][2], c_[mt][nt][3]);
                    biasacc[mt][1] += pv0 * c_[mt][nt][2] + pv1 * c_[mt][nt][3];
                }
            }
        }
#pragma unroll
        for (int mt = 0; mt < 2; ++mt)
#pragma unroll
            for (int half = 0; half < 2; ++half) {
                float p = biasacc[mt][half];
                p += __shfl_xor_sync(0xffffffffu, p, 1);
                p += __shfl_xor_sync(0xffffffffu, p, 2);
                int m = m0 + wm * 32 + mt * 16 + gi + half * 8;
                if (ti == 0 && m < RR) atomicAdd(&g_vr[m * 8 + h], p);
            }
    }
}

// ============================================================================
// Fused attention (unchanged from R13)
// ============================================================================
#define EW  36
#define EH2 72
#define CH  128
#define TFW 4608

__device__ __forceinline__ void ldg_A_k(uint32_t* r, const uint32_t* src,
                                        int wid, int gg, int tt) {
#pragma unroll
    for (int k = 0; k < 2; ++k) {
        int c = wid + (k << 4);
        int mt = c >> 2, ks = c & 3;
#pragma unroll
        for (int aidx = 0; aidx < 4; ++aidx) {
            int row = mt * 16 + (aidx & 1) * 8 + gg;
            int col = ks * 8 + (aidx >> 1) * 4 + tt;
            r[k * 4 + aidx] = src[(size_t)row * 32 + col];
        }
    }
}

__device__ __forceinline__ void ldg_A_rpe(uint32_t* r, const uint32_t* rc,
                                          int ubase, int wid, int gg, int tt) {
#pragma unroll
    for (int k = 0; k < 2; ++k) {
        int c = wid + (k << 4);
        int mt = c >> 2, ks = c & 3;
#pragma unroll
        for (int aidx = 0; aidx < 4; ++aidx) {
            int row = mt * 16 + (aidx & 1) * 8 + gg;
            int col = ks * 8 + (aidx >> 1) * 4 + tt;
            int u = ubase + row;
            r[k * 4 + aidx] = (u < RR) ? rc[(size_t)u * 256 + col] : 0u;
        }
    }
}

__device__ __forceinline__ void sts_A(uint32_t* buf, const uint32_t* r,
                                      int wid, int lane) {
#pragma unroll
    for (int k = 0; k < 2; ++k) {
        int c = wid + (k << 4);
        *(uint4*)&buf[(c * 32 + lane) * 4] =
            make_uint4(r[k * 4], r[k * 4 + 1], r[k * 4 + 2], r[k * 4 + 3]);
    }
}

__device__ __forceinline__ void ldg_B_v(uint32_t* r, const uint32_t* src, int tid) {
#pragma unroll
    for (int k = 0; k < 8; ++k) {
        int idx = k * 512 + tid;
        int dh = idx >> 6, w = idx & 63;
        r[k] = src[(size_t)dh * 256 + w];
    }
}

__device__ __forceinline__ void sts_B(uint32_t* buf, const uint32_t* r, int tid) {
#pragma unroll
    for (int k = 0; k < 8; ++k) {
        int idx = k * 512 + tid;
        int dh = idx >> 6, w = idx & 63;
        buf[dh * 68 + w] = r[k];
    }
}

__global__ void __launch_bounds__(512, 1)
attn_fp16_kernel(const float* __restrict__ tau_ptr) {
    extern __shared__ uint32_t smw[];
    uint32_t* e_h = smw;
    uint32_t* bdt = e_h + 512 * EW;
    uint32_t* Tf0 = bdt + 576 * EW;
    uint32_t* Tf1 = Tf0 + TFW;
    float* uks  = (float*)(Tf1 + TFW);
    float* vrs  = uks + 512;
    float* red  = vrs + 576;
    float* rowm = red + 1024;
    float* rowl = rowm + 64;
    uint32_t* Tf[2] = {Tf0, Tf1};
    __half* bdth = (__half*)bdt;

    const int bh = blockIdx.y, h = bh & 7, b = bh >> 3;
    const int i0 = blockIdx.x * 64;
    const int tid = threadIdx.x, lane = tid & 31, wid = tid >> 5;
    const int gi = lane >> 2, ti = lane & 3;
    const int wm = wid >> 2, wn = wid & 3;

    const uint32_t* kbase = (const uint32_t*)g_k + (size_t)bh * TT * 32;
    const uint32_t* vTbase = (const uint32_t*)g_vT + (size_t)bh * 64 * 256;
    const uint32_t* rc = (const uint32_t*)g_rpe + h * 32;
    const uint32_t* qg = (const uint32_t*)g_q + ((size_t)bh * TT + i0) * 32;

    uint32_t r[8];
    uint32_t qreg[2][4][2];

    ldg_A_rpe(r, rc, i0, wid, gi, ti);
#pragma unroll
    for (int n = 0; n < 2; ++n) {
        int irow = (wn * 2 + n) * 8 + gi;
#pragma unroll
        for (int ks = 0; ks < 4; ++ks) {
            qreg[n][ks][0] = qg[irow * 32 + ks * 8 + ti];
            qreg[n][ks][1] = qg[irow * 32 + ks * 8 + 4 + ti];
        }
    }
    uks[tid] = g_uk[bh * 512 + tid];
    for (int s = tid; s < 576; s += 512) {
        int u = i0 + s;
        vrs[s] = (u < RR) ? g_vr[u * 8 + h] : 0.f;
    }
    sts_A(Tf[0], r, wid, lane);
    __syncthreads();

#pragma unroll
    for (int ch = 0; ch < 5; ++ch) {
        if (ch < 4) ldg_A_rpe(r, rc, i0 + (ch + 1) * CH, wid, gi, ti);
        else        ldg_A_k(r, kbase, wid, gi, ti);

        if (!(ch == 4 && wm >= 2)) {
            float c_[2][2][4] = {};
            const uint32_t* cur = Tf[ch & 1];
#pragma unroll
            for (int ks = 0; ks < 4; ++ks) {
                uint32_t a[2][4];
#pragma unroll
                for (int mt = 0; mt < 2; ++mt) {
                    int mtg = wm * 2 + mt;
                    uint4 av = *(const uint4*)&cur[((mtg * 4 + ks) * 32 + lane) * 4];
                    a[mt][0] = av.x; a[mt][1] = av.y; a[mt][2] = av.z; a[mt][3] = av.w;
                }
#pragma unroll
                for (int n = 0; n < 2; ++n) {
                    mma16(c_[0][n], a[0], qreg[n][ks]);
                    mma16(c_[1][n], a[1], qreg[n][ks]);
                }
            }
#pragma unroll
            for (int mt = 0; mt < 2; ++mt) {
                int u = ch * CH + wm * 32 + mt * 16 + gi;
#pragma unroll
                for (int n = 0; n < 2; ++n) {
                    int iw = wn * 8 + n * 4 + ti;
                    bdt[u * EW + iw]       = packh2(c_[mt][n][0], c_[mt][n][1]);
                    bdt[(u + 8) * EW + iw] = packh2(c_[mt][n][2], c_[mt][n][3]);
                }
            }
        }
        sts_A(Tf[(ch + 1) & 1], r, wid, lane);
        __syncthreads();
    }

    const float scale = 0.125f;
    const float tauf = expf(tau_ptr[0]);
#pragma unroll
    for (int jc = 0; jc < 4; ++jc) {
        if (jc < 3) ldg_A_k(r, kbase + (size_t)(jc + 1) * CH * 32, wid, gi, ti);
        else        ldg_B_v(r, vTbase, tid);

        float c_[2][2][4] = {};
        const uint32_t* cur = Tf[(jc ^ 1) & 1];
#pragma unroll
        for (int ks = 0; ks < 4; ++ks) {
            uint32_t a[2][4];
#pragma unroll
            for (int mt = 0; mt < 2; ++mt) {
                int mtg = wm * 2 + mt;
                uint4 av = *(const uint4*)&cur[((mtg * 4 + ks) * 32 + lane) * 4];
                a[mt][0] = av.x; a[mt][1] = av.y; a[mt][2] = av.z; a[mt][3] = av.w;
            }
#pragma unroll
            for (int n = 0; n < 2; ++n) {
                mma16(c_[0][n], a[0], qreg[n][ks]);
                mma16(c_[1][n], a[1], qreg[n][ks]);
            }
        }
#pragma unroll
        for (int mt = 0; mt < 2; ++mt) {
            int j = jc * CH + wm * 32 + mt * 16 + gi;
            float uk0 = uks[j], uk1 = uks[j + 8];
#pragma unroll
            for (int n = 0; n < 2; ++n) {
                int ii = wn * 16 + n * 8 + 2 * ti;
                int iw = wn * 8 + n * 4 + ti;
#pragma unroll
                for (int rr = 0; rr < 2; ++rr) {
                    int jj = j + rr * 8;
                    float ukv = rr ? uk1 : uk0;
                    int ur0 = ii - jj + 511;
                    int ur1 = ur0 + 1;
                    float bd0 = __half2float(bdth[ur0 * EH2 + ii]);
                    float bd1 = __half2float(bdth[ur1 * EH2 + ii + 1]);
                    float v0 = (c_[mt][n][rr * 2]     + bd0 + ukv + vrs[ur0]) * scale;
                    float v1 = (c_[mt][n][rr * 2 + 1] + bd1 + ukv + vrs[ur1]) * scale;
                    if (jj == i0 + ii)     v0 = -FLT_MAX;
                    if (jj == i0 + ii + 1) v1 = -FLT_MAX;
                    e_h[jj * EW + iw] = packh2(v0 * tauf, v1 * tauf);
                }
            }
        }
        if (jc < 3) sts_A(Tf[jc & 1], r, wid, lane);
        else        sts_B(Tf[1], r, tid);
        __syncthreads();
    }

    {
        int cp = tid & 31, seg = tid >> 5;
        float m0 = -FLT_MAX, m1 = -FLT_MAX;
        for (int jj = 0; jj < 32; ++jj) {
            int j = seg * 32 + jj;
            __half2 hv = *(__half2*)&e_h[j * EW + cp];
            float2 f = __half22float2(hv);
            m0 = fmaxf(m0, f.x); m1 = fmaxf(m1, f.y);
        }
        red[seg * 64 + 2 * cp]     = m0;
        red[seg * 64 + 2 * cp + 1] = m1;
        __syncthreads();
        if (tid < 64) {
            float m = red[tid];
#pragma unroll
            for (int s = 1; s < 16; ++s) m = fmaxf(m, red[s * 64 + tid]);
            rowm[tid] = m;
        }
        __syncthreads();
        m0 = rowm[2 * cp]; m1 = rowm[2 * cp + 1];
        float s0 = 0.f, s1 = 0.f;
        for (int jj = 0; jj < 32; ++jj) {
            int j = seg * 32 + jj;
            __half2 hv = *(__half2*)&e_h[j * EW + cp];
            float2 f = __half22float2(hv);
            float p0 = __expf(f.x - m0), p1 = __expf(f.y - m1);
            e_h[j * EW + cp] = packh2(p0, p1);
            s0 += p0; s1 += p1;
        }
        red[seg * 64 + 2 * cp]     = s0;
        red[seg * 64 + 2 * cp + 1] = s1;
        __syncthreads();
        if (tid < 64) {
            float s = 0.f;
#pragma unroll
            for (int ss = 0; ss < 16; ++ss) s += red[ss * 64 + tid];
            rowl[tid] = s;
        }
        __syncthreads();
    }

    float o_[2][4] = {};
    const int pwm = wid >> 2;
    const int pwn = wid & 3;
    const uint32_t ehb = smem_u32(e_h);
    const int grp = lane >> 3, lr = lane & 7;
    const int rsel = (grp & 2) ? 8 : 0;
    const int csel = (grp & 1) ? 8 : 0;
    const int i0w = pwm * 16 + csel;
    const int vbrow = lr + ((lane >> 4) & 1) * 8;
    const int vbcol = ((lane >> 3) & 1) * 4;
#pragma unroll
    for (int jc = 0; jc < 4; ++jc) {
        if (jc < 3) ldg_B_v(r, vTbase + (size_t)(jc + 1) * 64, tid);

        const uint32_t* cur = Tf[(jc ^ 1) & 1];
        const uint32_t curb = smem_u32(cur);
#pragma unroll
        for (int ks = 0; ks < 8; ++ks) {
            int jb = jc * CH + ks * 16;
            uint32_t addr = ehb + (uint32_t)(((jb + rsel + lr) * EH2 + i0w) * 2);
            uint32_t a[4];
            asm volatile(
                "ldmatrix.sync.aligned.m8n8.x4.trans.shared.b16 {%0,%1,%2,%3}, [%4];"
                : "=r"(a[0]), "=r"(a[1]), "=r"(a[2]), "=r"(a[3]) : "r"(addr));
            uint32_t bq[4];
            ldm_x4(bq, curb + (uint32_t)(((pwn * 16 + vbrow) * 68 + ks * 8 + vbcol) * 4));
            mma16(o_[0], a, &bq[0]);
            mma16(o_[1], a, &bq[2]);
        }
        if (jc < 3) sts_B(Tf[jc & 1], r, tid);
        __syncthreads();
    }

    {
        int i1 = pwm * 16 + gi, i2 = i1 + 8;
        float inv1 = 1.f / rowl[i1];
        float inv2 = 1.f / rowl[i2];
#pragma unroll
        for (int n = 0; n < 2; ++n) {
            int dh = pwn * 16 + n * 8 + 2 * ti;
            size_t o1 = ((size_t)(i0 + i1) * 8 + b) * 512 + h * 64 + dh;
            size_t o2 = ((size_t)(i0 + i2) * 8 + b) * 512 + h * 64 + dh;
            *(uint32_t*)&g_aoh[o1] = packh2(o_[n][0] * inv1, o_[n][1] * inv1);
            *(uint32_t*)&g_aoh[o2] = packh2(o_[n][2] * inv2, o_[n][3] * inv2);
        }
    }
}

// ============================================================================
// Output projection (unchanged)
// ============================================================================
__global__ void __launch_bounds__(256, 3)
out_fp16_kernel(const float* __restrict__ bias, float* __restrict__ out) {
    __shared__ uint32_t As[128 * 36];
    __shared__ uint32_t Bs[64 * 36];
    const int bid = blockIdx.x, tid = threadIdx.x;
    const int m0 = (bid / 8) * 128, n0 = (bid % 8) * 64;
    const int lane = tid & 31, wid = tid >> 5;
    const int gi = lane >> 2, ti = lane & 3;
    const int wm = wid >> 1, wn = wid & 1;

    const int lr = lane & 7;
    const int arow = lr + ((lane >> 3) & 1) * 8;
    const int acol = (lane >> 4) * 4;
    const int brow = lr + ((lane >> 4) & 1) * 8;
    const int bcol = ((lane >> 3) & 1) * 4;
    const uint32_t asb = smem_u32(As);
    const uint32_t bsb = smem_u32(Bs);

    const uint32_t* aw = (const uint32_t*)g_aoh;
    const uint32_t* bw = (const uint32_t*)g_woh;

    float c_[2][4][4] = {};

    for (int k0 = 0; k0 < 8; ++k0) {
#pragma unroll
        for (int rep = 0; rep < 4; ++rep) {
            int s = rep * 256 + tid;
            int row = s >> 3, seg = s & 7;
            *(uint4*)&As[row * 36 + seg * 4] =
                *(const uint4*)&aw[(size_t)(m0 + row) * 256 + k0 * 32 + seg * 4];
        }
#pragma unroll
        for (int rep = 0; rep < 2; ++rep) {
            int s = rep * 256 + tid;
            int row = s >> 3, seg = s & 7;
            *(uint4*)&Bs[row * 36 + seg * 4] =
                *(const uint4*)&bw[(size_t)(n0 + row) * 256 + k0 * 32 + seg * 4];
        }
        __syncthreads();
#pragma unroll
        for (int kb = 0; kb < 4; ++kb) {
            uint32_t a[2][4], bq[2][4];
#pragma unroll
            for (int mt = 0; mt < 2; ++mt)
                ldm_x4(a[mt], asb + (uint32_t)(((wm * 32 + mt * 16 + arow) * 36
                                                + kb * 8 + acol) * 4));
#pragma unroll
            for (int p = 0; p < 2; ++p)
                ldm_x4(bq[p], bsb + (uint32_t)(((wn * 32 + p * 16 + brow) * 36
                                                + kb * 8 + bcol) * 4));
#pragma unroll
            for (int mt = 0; mt < 2; ++mt)
#pragma unroll
                for (int p = 0; p < 2; ++p) {
                    mma16(c_[mt][p * 2],     a[mt], &bq[p][0]);
                    mma16(c_[mt][p * 2 + 1], a[mt], &bq[p][2]);
                }
        }
        __syncthreads();
    }

#pragma unroll
    for (int mt = 0; mt < 2; ++mt) {
        int m = m0 + wm * 32 + mt * 16 + gi;
#pragma unroll
        for (int nt = 0; nt < 4; ++nt) {
            int n = n0 + wn * 32 + nt * 8 + 2 * ti;
            float b0 = bias[n], b1 = bias[n + 1];
            *(float2*)&out[(size_t)m * 512 + n] =
                make_float2(c_[mt][nt][0] + b0, c_[mt][nt][1] + b1);
            *(float2*)&out[(size_t)(m + 8) * 512 + n] =
                make_float2(c_[mt][nt][2] + b0, c_[mt][nt][3] + b1);
        }
    }
}

// ============================================================================
extern "C" void kernel_launch(void* const* d_in, const int* in_sizes, int n_in,
                              void* d_out, int out_size) {
    const float* x     = (const float*)d_in[0];
    const float* Wqkv  = (const float*)d_in[1];
    const float* Wpos  = (const float*)d_in[2];
    const float* pos_u = (const float*)d_in[3];
    const float* pos_v = (const float*)d_in[4];
    const float* Wout  = (const float*)d_in[5];
    const float* bout  = (const float*)d_in[6];
    const float* ltau  = (const float*)d_in[7];
    float* out = (float*)d_out;

    void *ukp, *vrp;
    cudaGetSymbolAddress(&ukp, g_uk);
    cudaGetSymbolAddress(&vrp, g_vr);
    cudaMemsetAsync(ukp, 0, BHN * TT * sizeof(float));
    cudaMemsetAsync(vrp, 0, RR * HH * sizeof(float));

    prep_kernel<<<1280, 256>>>(Wqkv, Wpos, Wout);
    gemm_fused_kernel<<<832, 256>>>(x, pos_u, pos_v);

    const size_t smem = (size_t)(512 * EW + 576 * EW + 2 * TFW
                                 + 512 + 576 + 1024 + 64 + 64) * sizeof(uint32_t);
    cudaFuncSetAttribute(attn_fp16_kernel, cudaFuncAttributeMaxDynamicSharedMemorySize, (int)smem);
    attn_fp16_kernel<<<dim3(8, 64), 512, smem>>>(ltau);

    out_fp16_kernel<<<256, 256>>>(bout, out);
}

// round 15
// speedup vs baseline: 1.0211x; 1.0211x over previous
#include <cuda_runtime.h>
#include <cuda_fp16.h>
#include <math.h>
#include <float.h>
#include <stdint.h>

#define TT   512
#define BB   8
#define DD   512
#define HH   8
#define DHH  64
#define RR   1023
#define BHN  64
#define MROWS 4096

// ---------------- scratch (fp16 payloads) ----------------
__device__ __half g_q[BHN * TT * DHH];      // [b*8+h][t][dh]
__device__ __half g_k[BHN * TT * DHH];
__device__ __half g_vT[BHN * DHH * TT];     // [b*8+h][dh][t]
__device__ __half g_rpe[RR * DD];           // [r][h*64+dh]
__device__ __half g_xh[MROWS * DD];
__device__ __half g_wqh[1536 * 512];        // W_qkv^T [n][k]
__device__ __half g_wph[512 * 512];         // W_pos^T [n][k]
__device__ __half g_woh[512 * 512];         // W_out^T [n][k]
__device__ __half g_aoh[MROWS * DD];        // attention out (t,b,d), half
__device__ float  g_uk[BHN * TT];
__device__ float  g_vr[RR * HH];

__device__ __forceinline__ void mma16(float* c, const uint32_t* a, const uint32_t* b) {
    asm volatile(
        "mma.sync.aligned.m16n8k16.row.col.f32.f16.f16.f32 "
        "{%0,%1,%2,%3},{%4,%5,%6,%7},{%8,%9},{%0,%1,%2,%3};"
        : "+f"(c[0]), "+f"(c[1]), "+f"(c[2]), "+f"(c[3])
        : "r"(a[0]), "r"(a[1]), "r"(a[2]), "r"(a[3]), "r"(b[0]), "r"(b[1]));
}

__device__ __forceinline__ uint32_t packh2(float lo, float hi) {
    __half2 h = __floats2half2_rn(lo, hi);
    return *(uint32_t*)&h;
}

__device__ __forceinline__ uint32_t smem_u32(const void* p) {
    uint32_t a;
    asm("{ .reg .u64 t; cvta.to.shared.u64 t, %1; cvt.u32.u64 %0, t; }" : "=r"(a) : "l"(p));
    return a;
}

__device__ __forceinline__ void ldm_x4(uint32_t* d, uint32_t addr) {
    asm volatile(
        "ldmatrix.sync.aligned.m8n8.x4.shared.b16 {%0,%1,%2,%3}, [%4];"
        : "=r"(d[0]), "=r"(d[1]), "=r"(d[2]), "=r"(d[3]) : "r"(addr));
}

// ============================================================================
// PREP (fused): blocks [0,2048) xhalf; [2048,2816) Wqkv^T; [2816,3072) Wpos^T;
// [3072,3328) Wout^T.
// ============================================================================
__global__ void __launch_bounds__(256)
prep_kernel(const float* __restrict__ x, const float* __restrict__ Wqkv,
            const float* __restrict__ Wpos, const float* __restrict__ Wout) {
    __shared__ float t[32][33];
    int bid = blockIdx.x, tid = threadIdx.x;

    if (bid < 2048) {
        int i = bid * 256 + tid;
        float4 v = *(const float4*)&x[(size_t)i * 4];
        *(uint32_t*)&g_xh[(size_t)i * 4]     = packh2(v.x, v.y);
        *(uint32_t*)&g_xh[(size_t)i * 4 + 2] = packh2(v.z, v.w);
        return;
    }

    const float* src; __half* dst; int N, bx, by;
    if (bid < 2816)      { int b = bid - 2048; src = Wqkv; dst = g_wqh; N = 1536; bx = b % 48, by = b / 48; }
    else if (bid < 3072) { int b = bid - 2816; src = Wpos; dst = g_wph; N = 512;  bx = b % 16, by = b / 16; }
    else                 { int b = bid - 3072; src = Wout; dst = g_woh; N = 512;  bx = b % 16, by = b / 16; }

    int n0 = bx * 32, k0 = by * 32;
    int tx = tid & 31, ty = tid >> 5;
    for (int r = ty; r < 32; r += 8)
        t[r][tx] = src[(size_t)(k0 + r) * N + n0 + tx];
    __syncthreads();
    for (int r = ty; r < 32; r += 8)
        dst[(size_t)(n0 + r) * 512 + k0 + tx] = __float2half(t[tx][r]);
}

// ============================================================================
// FUSED GEMM: QKV + rpe. 128x64 tile. Register-prefetch pipeline, occ 2.
// ============================================================================
__global__ void __launch_bounds__(256, 2)
gemm_fused_kernel() {
    __shared__ uint32_t As[128 * 36];
    __shared__ uint32_t Bs[64 * 36];
    __shared__ float freqs[512];
    const int bid = blockIdx.x, tid = threadIdx.x;
    const int lane = tid & 31, wid = tid >> 5;
    const int wm = wid >> 1, wn = wid & 1;
    const int gi = lane >> 2, ti = lane & 3;

    const int lr = lane & 7;
    const int arow = lr + ((lane >> 3) & 1) * 8;
    const int acol = (lane >> 4) * 4;
    const int brow = lr + ((lane >> 4) & 1) * 8;
    const int bcol = ((lane >> 3) & 1) * 4;
    const uint32_t asb = smem_u32(As);
    const uint32_t bsb = smem_u32(Bs);

    const bool is_rpe = (bid >= 768);
    int m0, n0;
    const uint32_t *aw = 0, *bw;
    if (!is_rpe) {
        m0 = (bid / 24) * 128; n0 = (bid % 24) * 64;
        aw = (const uint32_t*)g_xh; bw = (const uint32_t*)g_wqh;
    } else {
        int b = bid - 768;
        m0 = (b / 8) * 128; n0 = (b % 8) * 64;
        bw = (const uint32_t*)g_wph;
        for (int s = tid; s < 512; s += 256) {
            int cc = s & 255;
            freqs[s] = __expf(-9.210340371976184f * (float)cc * (1.0f / 256.0f));
        }
        __syncthreads();
    }

    float c_[2][4][4] = {};
    uint32_t ra[16], rb[8];

    // ---- prologue: stage chunk 0 into registers ----
    if (!is_rpe) {
#pragma unroll
        for (int rep = 0; rep < 4; ++rep) {
            int s = rep * 256 + tid;
            int row = s >> 3, seg = s & 7;
            *(uint4*)&ra[rep * 4] =
                *(const uint4*)&aw[(size_t)(m0 + row) * 256 + seg * 4];
        }
    } else {
#pragma unroll
        for (int rep = 0; rep < 16; ++rep) {
            int s = rep * 256 + tid;
            int row = s >> 5, w = s & 31;
            int kg = 2 * w;
            float rel = (float)(m0 + row - 511);
            float a0 = rel * freqs[kg], a1 = rel * freqs[kg + 1];
            float f0 = (kg < 256) ? sinf(a0) : cosf(a0);
            float f1 = (kg + 1 < 256) ? sinf(a1) : cosf(a1);
            ra[rep] = packh2(f0, f1);
        }
    }
#pragma unroll
    for (int rep = 0; rep < 2; ++rep) {
        int s = rep * 256 + tid;
        int row = s >> 3, seg = s & 7;
        *(uint4*)&rb[rep * 4] =
            *(const uint4*)&bw[(size_t)(n0 + row) * 256 + seg * 4];
    }

    for (int k0 = 0; k0 < 8; ++k0) {
        // ---- commit staged registers to smem ----
        if (!is_rpe) {
#pragma unroll
            for (int rep = 0; rep < 4; ++rep) {
                int s = rep * 256 + tid;
                int row = s >> 3, seg = s & 7;
                *(uint4*)&As[row * 36 + seg * 4] = *(uint4*)&ra[rep * 4];
            }
        } else {
#pragma unroll
            for (int rep = 0; rep < 16; ++rep) {
                int s = rep * 256 + tid;
                int row = s >> 5, w = s & 31;
                As[row * 36 + w] = ra[rep];
            }
        }
#pragma unroll
        for (int rep = 0; rep < 2; ++rep) {
            int s = rep * 256 + tid;
            int row = s >> 3, seg = s & 7;
            *(uint4*)&Bs[row * 36 + seg * 4] = *(uint4*)&rb[rep * 4];
        }
        __syncthreads();

        // ---- prefetch chunk k0+1 while mma runs ----
        if (k0 < 7) {
            int kn = k0 + 1;
            if (!is_rpe) {
#pragma unroll
                for (int rep = 0; rep < 4; ++rep) {
                    int s = rep * 256 + tid;
                    int row = s >> 3, seg = s & 7;
                    *(uint4*)&ra[rep * 4] =
                        *(const uint4*)&aw[(size_t)(m0 + row) * 256 + kn * 32 + seg * 4];
                }
            } else {
#pragma unroll
                for (int rep = 0; rep < 16; ++rep) {
                    int s = rep * 256 + tid;
                    int row = s >> 5, w = s & 31;
                    int kg = kn * 64 + 2 * w;
                    float rel = (float)(m0 + row - 511);
                    float a0 = rel * freqs[kg], a1 = rel * freqs[kg + 1];
                    float f0 = (kg < 256) ? sinf(a0) : cosf(a0);
                    float f1 = (kg + 1 < 256) ? sinf(a1) : cosf(a1);
                    ra[rep] = packh2(f0, f1);
                }
            }
#pragma unroll
            for (int rep = 0; rep < 2; ++rep) {
                int s = rep * 256 + tid;
                int row = s >> 3, seg = s & 7;
                *(uint4*)&rb[rep * 4] =
                    *(const uint4*)&bw[(size_t)(n0 + row) * 256 + kn * 32 + seg * 4];
            }
        }

#pragma unroll
        for (int kb = 0; kb < 4; ++kb) {
            uint32_t a[2][4], bq[2][4];
#pragma unroll
            for (int mt = 0; mt < 2; ++mt)
                ldm_x4(a[mt], asb + (uint32_t)(((wm * 32 + mt * 16 + arow) * 36
                                                + kb * 8 + acol) * 4));
#pragma unroll
            for (int p = 0; p < 2; ++p)
                ldm_x4(bq[p], bsb + (uint32_t)(((wn * 32 + p * 16 + brow) * 36
                                                + kb * 8 + bcol) * 4));
#pragma unroll
            for (int mt = 0; mt < 2; ++mt)
#pragma unroll
                for (int p = 0; p < 2; ++p) {
                    mma16(c_[mt][p * 2],     a[mt], &bq[p][0]);
                    mma16(c_[mt][p * 2 + 1], a[mt], &bq[p][2]);
                }
        }
        __syncthreads();
    }

    if (!is_rpe) {
#pragma unroll
        for (int mt = 0; mt < 2; ++mt) {
            int m = m0 + wm * 32 + mt * 16 + gi;
#pragma unroll
            for (int nt = 0; nt < 4; ++nt) {
                int n = n0 + wn * 32 + nt * 8 + 2 * ti;
                int part = n >> 9, hh = (n >> 6) & 7, dh = n & 63;
#pragma unroll
                for (int half = 0; half < 2; ++half) {
                    int mm = m + half * 8;
                    float v0 = c_[mt][nt][half * 2], v1 = c_[mt][nt][half * 2 + 1];
                    int tr = mm >> 3, bi = mm & 7;
                    int bh = bi * 8 + hh;
                    if (part == 2) {
                        g_vT[((size_t)bh * 64 + dh) * 512 + tr]     = __float2half(v0);
                        g_vT[((size_t)bh * 64 + dh + 1) * 512 + tr] = __float2half(v1);
                    } else {
                        __half* dst = (part == 0) ? g_q : g_k;
                        *(uint32_t*)&dst[((size_t)bh * 512 + tr) * 64 + dh] = packh2(v0, v1);
                    }
                }
            }
        }
    } else {
#pragma unroll
        for (int mt = 0; mt < 2; ++mt) {
            int m = m0 + wm * 32 + mt * 16 + gi;
#pragma unroll
            for (int nt = 0; nt < 4; ++nt) {
                int n = n0 + wn * 32 + nt * 8 + 2 * ti;
                if (m < RR)
                    *(uint32_t*)&g_rpe[(size_t)m * 512 + n] = packh2(c_[mt][nt][0], c_[mt][nt][1]);
                if (m + 8 < RR)
                    *(uint32_t*)&g_rpe[(size_t)(m + 8) * 512 + n] = packh2(c_[mt][nt][2], c_[mt][nt][3]);
            }
        }
    }
}

// ============================================================================
// BIAS (fused)
// ============================================================================
__global__ void __launch_bounds__(256)
bias_kernel(const float* __restrict__ pos_u, const float* __restrict__ pos_v) {
    int bid = blockIdx.x, tid = threadIdx.x;
    if (bid < 512) {
        int gid = bid * 256 + tid;
        int id = gid >> 2, part = gid & 3;
        int h = (id >> 9) & 7;
        const __half2* kp = (const __half2*)(g_k + (size_t)id * 64) + part * 8;
        const float* up = pos_u + h * 64 + part * 16;
        float acc = 0.f;
#pragma unroll
        for (int s = 0; s < 8; ++s) {
            float2 kf = __half22float2(kp[s]);
            acc += kf.x * up[2 * s] + kf.y * up[2 * s + 1];
        }
        acc += __shfl_xor_sync(0xffffffffu, acc, 1);
        acc += __shfl_xor_sync(0xffffffffu, acc, 2);
        if (part == 0) g_uk[id] = acc;
    } else {
        int gid = (bid - 512) * 256 + tid;
        int id = gid >> 2, part = gid & 3;
        if (id >= RR * HH) return;
        int r = id >> 3, h = id & 7;
        const __half2* rp = (const __half2*)(g_rpe + (size_t)r * 512 + h * 64) + part * 8;
        const float* vp = pos_v + h * 64 + part * 16;
        float acc = 0.f;
#pragma unroll
        for (int s = 0; s < 8; ++s) {
            float2 rf = __half22float2(rp[s]);
            acc += rf.x * vp[2 * s] + rf.y * vp[2 * s + 1];
        }
        acc += __shfl_xor_sync(0xffffffffu, acc, 1);
        acc += __shfl_xor_sync(0xffffffffu, acc, 2);
        if (part == 0) g_vr[id] = acc;
    }
}

// ============================================================================
// Fused attention (unchanged from R13)
// ============================================================================
#define EW  36
#define EH2 72
#define CH  128
#define TFW 4608

__device__ __forceinline__ void ldg_A_k(uint32_t* r, const uint32_t* src,
                                        int wid, int gg, int tt) {
#pragma unroll
    for (int k = 0; k < 2; ++k) {
        int c = wid + (k << 4);
        int mt = c >> 2, ks = c & 3;
#pragma unroll
        for (int aidx = 0; aidx < 4; ++aidx) {
            int row = mt * 16 + (aidx & 1) * 8 + gg;
            int col = ks * 8 + (aidx >> 1) * 4 + tt;
            r[k * 4 + aidx] = src[(size_t)row * 32 + col];
        }
    }
}

__device__ __forceinline__ void ldg_A_rpe(uint32_t* r, const uint32_t* rc,
                                          int ubase, int wid, int gg, int tt) {
#pragma unroll
    for (int k = 0; k < 2; ++k) {
        int c = wid + (k << 4);
        int mt = c >> 2, ks = c & 3;
#pragma unroll
        for (int aidx = 0; aidx < 4; ++aidx) {
            int row = mt * 16 + (aidx & 1) * 8 + gg;
            int col = ks * 8 + (aidx >> 1) * 4 + tt;
            int u = ubase + row;
            r[k * 4 + aidx] = (u < RR) ? rc[(size_t)u * 256 + col] : 0u;
        }
    }
}

__device__ __forceinline__ void sts_A(uint32_t* buf, const uint32_t* r,
                                      int wid, int lane) {
#pragma unroll
    for (int k = 0; k < 2; ++k) {
        int c = wid + (k << 4);
        *(uint4*)&buf[(c * 32 + lane) * 4] =
            make_uint4(r[k * 4], r[k * 4 + 1], r[k * 4 + 2], r[k * 4 + 3]);
    }
}

__device__ __forceinline__ void ldg_B_v(uint32_t* r, const uint32_t* src, int tid) {
#pragma unroll
    for (int k = 0; k < 8; ++k) {
        int idx = k * 512 + tid;
        int dh = idx >> 6, w = idx & 63;
        r[k] = src[(size_t)dh * 256 + w];
    }
}

__device__ __forceinline__ void sts_B(uint32_t* buf, const uint32_t* r, int tid) {
#pragma unroll
    for (int k = 0; k < 8; ++k) {
        int idx = k * 512 + tid;
        int dh = idx >> 6, w = idx & 63;
        buf[dh * 68 + w] = r[k];
    }
}

__global__ void __launch_bounds__(512, 1)
attn_fp16_kernel(const float* __restrict__ tau_ptr) {
    extern __shared__ uint32_t smw[];
    uint32_t* e_h = smw;
    uint32_t* bdt = e_h + 512 * EW;
    uint32_t* Tf0 = bdt + 576 * EW;
    uint32_t* Tf1 = Tf0 + TFW;
    float* uks  = (float*)(Tf1 + TFW);
    float* vrs  = uks + 512;
    float* red  = vrs + 576;
    float* rowm = red + 1024;
    float* rowl = rowm + 64;
    uint32_t* Tf[2] = {Tf0, Tf1};
    __half* bdth = (__half*)bdt;

    const int bh = blockIdx.y, h = bh & 7, b = bh >> 3;
    const int i0 = blockIdx.x * 64;
    const int tid = threadIdx.x, lane = tid & 31, wid = tid >> 5;
    const int gi = lane >> 2, ti = lane & 3;
    const int wm = wid >> 2, wn = wid & 3;

    const uint32_t* kbase = (const uint32_t*)g_k + (size_t)bh * TT * 32;
    const uint32_t* vTbase = (const uint32_t*)g_vT + (size_t)bh * 64 * 256;
    const uint32_t* rc = (const uint32_t*)g_rpe + h * 32;
    const uint32_t* qg = (const uint32_t*)g_q + ((size_t)bh * TT + i0) * 32;

    uint32_t r[8];
    uint32_t qreg[2][4][2];

    ldg_A_rpe(r, rc, i0, wid, gi, ti);
#pragma unroll
    for (int n = 0; n < 2; ++n) {
        int irow = (wn * 2 + n) * 8 + gi;
#pragma unroll
        for (int ks = 0; ks < 4; ++ks) {
            qreg[n][ks][0] = qg[irow * 32 + ks * 8 + ti];
            qreg[n][ks][1] = qg[irow * 32 + ks * 8 + 4 + ti];
        }
    }
    uks[tid] = g_uk[bh * 512 + tid];
    for (int s = tid; s < 576; s += 512) {
        int u = i0 + s;
        vrs[s] = (u < RR) ? g_vr[u * 8 + h] : 0.f;
    }
    sts_A(Tf[0], r, wid, lane);
    __syncthreads();

#pragma unroll
    for (int ch = 0; ch < 5; ++ch) {
        if (ch < 4) ldg_A_rpe(r, rc, i0 + (ch + 1) * CH, wid, gi, ti);
        else        ldg_A_k(r, kbase, wid, gi, ti);

        if (!(ch == 4 && wm >= 2)) {
            float c_[2][2][4] = {};
            const uint32_t* cur = Tf[ch & 1];
#pragma unroll
            for (int ks = 0; ks < 4; ++ks) {
                uint32_t a[2][4];
#pragma unroll
                for (int mt = 0; mt < 2; ++mt) {
                    int mtg = wm * 2 + mt;
                    uint4 av = *(const uint4*)&cur[((mtg * 4 + ks) * 32 + lane) * 4];
                    a[mt][0] = av.x; a[mt][1] = av.y; a[mt][2] = av.z; a[mt][3] = av.w;
                }
#pragma unroll
                for (int n = 0; n < 2; ++n) {
                    mma16(c_[0][n], a[0], qreg[n][ks]);
                    mma16(c_[1][n], a[1], qreg[n][ks]);
                }
            }
#pragma unroll
            for (int mt = 0; mt < 2; ++mt) {
                int u = ch * CH + wm * 32 + mt * 16 + gi;
#pragma unroll
                for (int n = 0; n < 2; ++n) {
                    int iw = wn * 8 + n * 4 + ti;
                    bdt[u * EW + iw]       = packh2(c_[mt][n][0], c_[mt][n][1]);
                    bdt[(u + 8) * EW + iw] = packh2(c_[mt][n][2], c_[mt][n][3]);
                }
            }
        }
        sts_A(Tf[(ch + 1) & 1], r, wid, lane);
        __syncthreads();
    }

    const float scale = 0.125f;
    const float tauf = expf(tau_ptr[0]);
#pragma unroll
    for (int jc = 0; jc < 4; ++jc) {
        if (jc < 3) ldg_A_k(r, kbase + (size_t)(jc + 1) * CH * 32, wid, gi, ti);
        else        ldg_B_v(r, vTbase, tid);

        float c_[2][2][4] = {};
        const uint32_t* cur = Tf[(jc ^ 1) & 1];
#pragma unroll
        for (int ks = 0; ks < 4; ++ks) {
            uint32_t a[2][4];
#pragma unroll
            for (int mt = 0; mt < 2; ++mt) {
                int mtg = wm * 2 + mt;
                uint4 av = *(const uint4*)&cur[((mtg * 4 + ks) * 32 + lane) * 4];
                a[mt][0] = av.x; a[mt][1] = av.y; a[mt][2] = av.z; a[mt][3] = av.w;
            }
#pragma unroll
            for (int n = 0; n < 2; ++n) {
                mma16(c_[0][n], a[0], qreg[n][ks]);
                mma16(c_[1][n], a[1], qreg[n][ks]);
            }
        }
#pragma unroll
        for (int mt = 0; mt < 2; ++mt) {
            int j = jc * CH + wm * 32 + mt * 16 + gi;
            float uk0 = uks[j], uk1 = uks[j + 8];
#pragma unroll
            for (int n = 0; n < 2; ++n) {
                int ii = wn * 16 + n * 8 + 2 * ti;
                int iw = wn * 8 + n * 4 + ti;
#pragma unroll
                for (int rr = 0; rr < 2; ++rr) {
                    int jj = j + rr * 8;
                    float ukv = rr ? uk1 : uk0;
                    int ur0 = ii - jj + 511;
                    int ur1 = ur0 + 1;
                    float bd0 = __half2float(bdth[ur0 * EH2 + ii]);
                    float bd1 = __half2float(bdth[ur1 * EH2 + ii + 1]);
                    float v0 = (c_[mt][n][rr * 2]     + bd0 + ukv + vrs[ur0]) * scale;
                    float v1 = (c_[mt][n][rr * 2 + 1] + bd1 + ukv + vrs[ur1]) * scale;
                    if (jj == i0 + ii)     v0 = -FLT_MAX;
                    if (jj == i0 + ii + 1) v1 = -FLT_MAX;
                    e_h[jj * EW + iw] = packh2(v0 * tauf, v1 * tauf);
                }
            }
        }
        if (jc < 3) sts_A(Tf[jc & 1], r, wid, lane);
        else        sts_B(Tf[1], r, tid);
        __syncthreads();
    }

    {
        int cp = tid & 31, seg = tid >> 5;
        float m0 = -FLT_MAX, m1 = -FLT_MAX;
        for (int jj = 0; jj < 32; ++jj) {
            int j = seg * 32 + jj;
            __half2 hv = *(__half2*)&e_h[j * EW + cp];
            float2 f = __half22float2(hv);
            m0 = fmaxf(m0, f.x); m1 = fmaxf(m1, f.y);
        }
        red[seg * 64 + 2 * cp]     = m0;
        red[seg * 64 + 2 * cp + 1] = m1;
        __syncthreads();
        if (tid < 64) {
            float m = red[tid];
#pragma unroll
            for (int s = 1; s < 16; ++s) m = fmaxf(m, red[s * 64 + tid]);
            rowm[tid] = m;
        }
        __syncthreads();
        m0 = rowm[2 * cp]; m1 = rowm[2 * cp + 1];
        float s0 = 0.f, s1 = 0.f;
        for (int jj = 0; jj < 32; ++jj) {
            int j = seg * 32 + jj;
            __half2 hv = *(__half2*)&e_h[j * EW + cp];
            float2 f = __half22float2(hv);
            float p0 = __expf(f.x - m0), p1 = __expf(f.y - m1);
            e_h[j * EW + cp] = packh2(p0, p1);
            s0 += p0; s1 += p1;
        }
        red[seg * 64 + 2 * cp]     = s0;
        red[seg * 64 + 2 * cp + 1] = s1;
        __syncthreads();
        if (tid < 64) {
            float s = 0.f;
#pragma unroll
            for (int ss = 0; ss < 16; ++ss) s += red[ss * 64 + tid];
            rowl[tid] = s;
        }
        __syncthreads();
    }

    float o_[2][4] = {};
    const int pwm = wid >> 2;
    const int pwn = wid & 3;
    const uint32_t ehb = smem_u32(e_h);
    const int grp = lane >> 3, lr = lane & 7;
    const int rsel = (grp & 2) ? 8 : 0;
    const int csel = (grp & 1) ? 8 : 0;
    const int i0w = pwm * 16 + csel;
    const int vbrow = lr + ((lane >> 4) & 1) * 8;
    const int vbcol = ((lane >> 3) & 1) * 4;
#pragma unroll
    for (int jc = 0; jc < 4; ++jc) {
        if (jc < 3) ldg_B_v(r, vTbase + (size_t)(jc + 1) * 64, tid);

        const uint32_t* cur = Tf[(jc ^ 1) & 1];
        const uint32_t curb = smem_u32(cur);
#pragma unroll
        for (int ks = 0; ks < 8; ++ks) {
            int jb = jc * CH + ks * 16;
            uint32_t addr = ehb + (uint32_t)(((jb + rsel + lr) * EH2 + i0w) * 2);
            uint32_t a[4];
            asm volatile(
                "ldmatrix.sync.aligned.m8n8.x4.trans.shared.b16 {%0,%1,%2,%3}, [%4];"
                : "=r"(a[0]), "=r"(a[1]), "=r"(a[2]), "=r"(a[3]) : "r"(addr));
            uint32_t bq[4];
            ldm_x4(bq, curb + (uint32_t)(((pwn * 16 + vbrow) * 68 + ks * 8 + vbcol) * 4));
            mma16(o_[0], a, &bq[0]);
            mma16(o_[1], a, &bq[2]);
        }
        if (jc < 3) sts_B(Tf[jc & 1], r, tid);
        __syncthreads();
    }

    {
        int i1 = pwm * 16 + gi, i2 = i1 + 8;
        float inv1 = 1.f / rowl[i1];
        float inv2 = 1.f / rowl[i2];
#pragma unroll
        for (int n = 0; n < 2; ++n) {
            int dh = pwn * 16 + n * 8 + 2 * ti;
            size_t o1 = ((size_t)(i0 + i1) * 8 + b) * 512 + h * 64 + dh;
            size_t o2 = ((size_t)(i0 + i2) * 8 + b) * 512 + h * 64 + dh;
            *(uint32_t*)&g_aoh[o1] = packh2(o_[n][0] * inv1, o_[n][1] * inv1);
            *(uint32_t*)&g_aoh[o2] = packh2(o_[n][2] * inv2, o_[n][3] * inv2);
        }
    }
}

// ============================================================================
// Output projection: register-prefetch pipeline, occ 2.
// ============================================================================
__global__ void __launch_bounds__(256, 2)
out_fp16_kernel(const float* __restrict__ bias, float* __restrict__ out) {
    __shared__ uint32_t As[128 * 36];
    __shared__ uint32_t Bs[64 * 36];
    const int bid = blockIdx.x, tid = threadIdx.x;
    const int m0 = (bid / 8) * 128, n0 = (bid % 8) * 64;
    const int lane = tid & 31, wid = tid >> 5;
    const int gi = lane >> 2, ti = lane & 3;
    const int wm = wid >> 1, wn = wid & 1;

    const int lr = lane & 7;
    const int arow = lr + ((lane >> 3) & 1) * 8;
    const int acol = (lane >> 4) * 4;
    const int brow = lr + ((lane >> 4) & 1) * 8;
    const int bcol = ((lane >> 3) & 1) * 4;
    const uint32_t asb = smem_u32(As);
    const uint32_t bsb = smem_u32(Bs);

    const uint32_t* aw = (const uint32_t*)g_aoh;
    const uint32_t* bw = (const uint32_t*)g_woh;

    float c_[2][4][4] = {};
    uint32_t ra[16], rb[8];

#pragma unroll
    for (int rep = 0; rep < 4; ++rep) {
        int s = rep * 256 + tid;
        int row = s >> 3, seg = s & 7;
        *(uint4*)&ra[rep * 4] = *(const uint4*)&aw[(size_t)(m0 + row) * 256 + seg * 4];
    }
#pragma unroll
    for (int rep = 0; rep < 2; ++rep) {
        int s = rep * 256 + tid;
        int row = s >> 3, seg = s & 7;
        *(uint4*)&rb[rep * 4] = *(const uint4*)&bw[(size_t)(n0 + row) * 256 + seg * 4];
    }

    for (int k0 = 0; k0 < 8; ++k0) {
#pragma unroll
        for (int rep = 0; rep < 4; ++rep) {
            int s = rep * 256 + tid;
            int row = s >> 3, seg = s & 7;
            *(uint4*)&As[row * 36 + seg * 4] = *(uint4*)&ra[rep * 4];
        }
#pragma unroll
        for (int rep = 0; rep < 2; ++rep) {
            int s = rep * 256 + tid;
            int row = s >> 3, seg = s & 7;
            *(uint4*)&Bs[row * 36 + seg * 4] = *(uint4*)&rb[rep * 4];
        }
        __syncthreads();

        if (k0 < 7) {
            int kn = k0 + 1;
#pragma unroll
            for (int rep = 0; rep < 4; ++rep) {
                int s = rep * 256 + tid;
                int row = s >> 3, seg = s & 7;
                *(uint4*)&ra[rep * 4] =
                    *(const uint4*)&aw[(size_t)(m0 + row) * 256 + kn * 32 + seg * 4];
            }
#pragma unroll
            for (int rep = 0; rep < 2; ++rep) {
                int s = rep * 256 + tid;
                int row = s >> 3, seg = s & 7;
                *(uint4*)&rb[rep * 4] =
                    *(const uint4*)&bw[(size_t)(n0 + row) * 256 + kn * 32 + seg * 4];
            }
        }

#pragma unroll
        for (int kb = 0; kb < 4; ++kb) {
            uint32_t a[2][4], bq[2][4];
#pragma unroll
            for (int mt = 0; mt < 2; ++mt)
                ldm_x4(a[mt], asb + (uint32_t)(((wm * 32 + mt * 16 + arow) * 36
                                                + kb * 8 + acol) * 4));
#pragma unroll
            for (int p = 0; p < 2; ++p)
                ldm_x4(bq[p], bsb + (uint32_t)(((wn * 32 + p * 16 + brow) * 36
                                                + kb * 8 + bcol) * 4));
#pragma unroll
            for (int mt = 0; mt < 2; ++mt)
#pragma unroll
                for (int p = 0; p < 2; ++p) {
                    mma16(c_[mt][p * 2],     a[mt], &bq[p][0]);
                    mma16(c_[mt][p * 2 + 1], a[mt], &bq[p][2]);
                }
        }
        __syncthreads();
    }

#pragma unroll
    for (int mt = 0; mt < 2; ++mt) {
        int m = m0 + wm * 32 + mt * 16 + gi;
#pragma unroll
        for (int nt = 0; nt < 4; ++nt) {
            int n = n0 + wn * 32 + nt * 8 + 2 * ti;
            float b0 = bias[n], b1 = bias[n + 1];
            *(float2*)&out[(size_t)m * 512 + n] =
                make_float2(c_[mt][nt][0] + b0, c_[mt][nt][1] + b1);
            *(float2*)&out[(size_t)(m + 8) * 512 + n] =
                make_float2(c_[mt][nt][2] + b0, c_[mt][nt][3] + b1);
        }
    }
}

// ============================================================================
extern "C" void kernel_launch(void* const* d_in, const int* in_sizes, int n_in,
                              void* d_out, int out_size) {
    const float* x     = (const float*)d_in[0];
    const float* Wqkv  = (const float*)d_in[1];
    const float* Wpos  = (const float*)d_in[2];
    const float* pos_u = (const float*)d_in[3];
    const float* pos_v = (const float*)d_in[4];
    const float* Wout  = (const float*)d_in[5];
    const float* bout  = (const float*)d_in[6];
    const float* ltau  = (const float*)d_in[7];
    float* out = (float*)d_out;

    prep_kernel<<<3328, 256>>>(x, Wqkv, Wpos, Wout);
    gemm_fused_kernel<<<832, 256>>>();
    bias_kernel<<<640, 256>>>(pos_u, pos_v);

    const size_t smem = (size_t)(512 * EW + 576 * EW + 2 * TFW
                                 + 512 + 576 + 1024 + 64 + 64) * sizeof(uint32_t);
    cudaFuncSetAttribute(attn_fp16_kernel, cudaFuncAttributeMaxDynamicSharedMemorySize, (int)smem);
    attn_fp16_kernel<<<dim3(8, 64), 512, smem>>>(ltau);

    out_fp16_kernel<<<256, 256>>>(bout, out);
}